// round 1
// baseline (speedup 1.0000x reference)
#include <cuda_runtime.h>

#define FULLMASK 0xFFFFFFFFu
#define KNN 16

// ---- packed f32x2 helpers (sm_103a FFMA2 path) ----
static __device__ __forceinline__ unsigned long long fma2(unsigned long long a,
                                                          unsigned long long b,
                                                          unsigned long long c) {
    unsigned long long d;
    asm("fma.rn.f32x2 %0, %1, %2, %3;" : "=l"(d) : "l"(a), "l"(b), "l"(c));
    return d;
}
static __device__ __forceinline__ unsigned long long pack2(float lo, float hi) {
    unsigned long long v;
    asm("mov.b64 %0, {%1, %2};"
        : "=l"(v) : "r"(__float_as_uint(lo)), "r"(__float_as_uint(hi)));
    return v;
}
static __device__ __forceinline__ void unpack2(unsigned long long v, float &lo, float &hi) {
    unsigned a, b;
    asm("mov.b64 {%0, %1}, %2;" : "=r"(a), "=r"(b) : "l"(v));
    lo = __uint_as_float(a);
    hi = __uint_as_float(b);
}

static __device__ __forceinline__ float sel8(float r0, float r1, float r2, float r3,
                                             float r4, float r5, float r6, float r7,
                                             int k) {
    float s01 = (k & 1) ? r1 : r0;
    float s23 = (k & 1) ? r3 : r2;
    float s45 = (k & 1) ? r5 : r4;
    float s67 = (k & 1) ? r7 : r6;
    float a = (k & 2) ? s23 : s01;
    float b = (k & 2) ? s67 : s45;
    return (k & 4) ? b : a;
}

__global__ void __launch_bounds__(256, 1)
knn_warpselect_kernel(const float* __restrict__ p, float* __restrict__ out,
                      int n, int padn, int iters) {
    extern __shared__ float smem[];
    float* xs = smem;
    float* ys = smem + padn;
    float* sq = smem + 2 * padn;

    const int tid = threadIdx.x;

    // One-time SoA load of the whole point set into shared memory.
    for (int j = tid; j < padn; j += blockDim.x) {
        if (j < n) {
            float x = p[3 * j];
            float y = p[3 * j + 1];
            xs[j] = x;
            ys[j] = y;
            sq[j] = fmaf(x, x, y * y);
        } else {
            xs[j] = 0.0f;
            ys[j] = 0.0f;
            sq[j] = 3.0e38f;  // sentinel: r = 3e38, never selected
        }
    }
    __syncthreads();

    const int lane = tid & 31;
    const int gw = blockIdx.x * (blockDim.x >> 5) + (tid >> 5);
    const int nwarps = gridDim.x * (blockDim.x >> 5);

    for (int q = gw; q < n; q += nwarps) {
        const float xq = xs[q];
        const float yq = ys[q];
        const float cx = -2.0f * xq;
        const float cy = -2.0f * yq;
        const unsigned long long cx2 = pack2(cx, cx);
        const unsigned long long cy2 = pack2(cy, cy);

        // ---- prime: warp-bitonic sort of first 32 candidates (r, idx) ----
        float lr;
        int li;
        {
            float r = fmaf(cx, xs[lane], fmaf(cy, ys[lane], sq[lane]));
            int idx = lane;
            if (idx == q) r = 3.0e38f;  // exclude self
#pragma unroll
            for (int k = 2; k <= 32; k <<= 1) {
#pragma unroll
                for (int j = k >> 1; j > 0; j >>= 1) {
                    float orv = __shfl_xor_sync(FULLMASK, r, j);
                    int oiv = __shfl_xor_sync(FULLMASK, idx, j);
                    bool up = ((lane & k) == 0);
                    bool lower = ((lane & j) == 0);
                    bool takeMin = (lower == up);
                    bool sw = takeMin ? (orv < r) : (orv > r);
                    if (sw) { r = orv; idx = oiv; }
                }
            }
            lr = r;   // lane l holds l-th smallest r of first 32 candidates
            li = idx;
        }
        float worst = __shfl_sync(FULLMASK, lr, KNN - 1);

        // ---- main scan: 8 candidates/lane/iter, register double-buffered ----
        int base = 32 + lane * 8;
        ulonglong2 xa = *reinterpret_cast<const ulonglong2*>(xs + base);
        ulonglong2 xb = *reinterpret_cast<const ulonglong2*>(xs + base + 4);
        ulonglong2 ya = *reinterpret_cast<const ulonglong2*>(ys + base);
        ulonglong2 yb = *reinterpret_cast<const ulonglong2*>(ys + base + 4);
        ulonglong2 sa = *reinterpret_cast<const ulonglong2*>(sq + base);
        ulonglong2 sb = *reinterpret_cast<const ulonglong2*>(sq + base + 4);

        for (int i = 0; i < iters; i++) {
            const int nbase = base + 256;
            // prefetch next tile (padding guarantees in-bounds)
            ulonglong2 nxa = *reinterpret_cast<const ulonglong2*>(xs + nbase);
            ulonglong2 nxb = *reinterpret_cast<const ulonglong2*>(xs + nbase + 4);
            ulonglong2 nya = *reinterpret_cast<const ulonglong2*>(ys + nbase);
            ulonglong2 nyb = *reinterpret_cast<const ulonglong2*>(ys + nbase + 4);
            ulonglong2 nsa = *reinterpret_cast<const ulonglong2*>(sq + nbase);
            ulonglong2 nsb = *reinterpret_cast<const ulonglong2*>(sq + nbase + 4);

            unsigned long long ra = fma2(cx2, xa.x, fma2(cy2, ya.x, sa.x));
            unsigned long long rb = fma2(cx2, xa.y, fma2(cy2, ya.y, sa.y));
            unsigned long long rc = fma2(cx2, xb.x, fma2(cy2, yb.x, sb.x));
            unsigned long long rd = fma2(cx2, xb.y, fma2(cy2, yb.y, sb.y));
            float r0, r1, r2, r3, r4, r5, r6, r7;
            unpack2(ra, r0, r1);
            unpack2(rb, r2, r3);
            unpack2(rc, r4, r5);
            unpack2(rd, r6, r7);

            float m = fminf(fminf(fminf(r0, r1), fminf(r2, r3)),
                            fminf(fminf(r4, r5), fminf(r6, r7)));
            unsigned hb = __ballot_sync(FULLMASK, m < worst);
            if (hb) {
                // build per-lane pass mask over the 8 screened candidates
                unsigned pm = 0;
                pm |= (r0 < worst) ? 1u : 0u;
                pm |= (r1 < worst) ? 2u : 0u;
                pm |= (r2 < worst) ? 4u : 0u;
                pm |= (r3 < worst) ? 8u : 0u;
                pm |= (r4 < worst) ? 16u : 0u;
                pm |= (r5 < worst) ? 32u : 0u;
                pm |= (r6 < worst) ? 64u : 0u;
                pm |= (r7 < worst) ? 128u : 0u;

                int k0 = __ffs(pm) - 1;
                float vs = sel8(r0, r1, r2, r3, r4, r5, r6, r7, k0);
                int vis = base + k0;

                unsigned act = __ballot_sync(FULLMASK, pm != 0);
                while (act) {
                    int src = __ffs(act) - 1;
                    float v = __shfl_sync(FULLMASK, vs, src);
                    int vi = __shfl_sync(FULLMASK, vis, src);
                    if (lane == src) {
                        pm &= pm - 1;
                        int k = __ffs(pm) - 1;
                        vs = sel8(r0, r1, r2, r3, r4, r5, r6, r7, k);
                        vis = base + k;
                    }
                    // re-check against (possibly tightened) threshold; skip self
                    if (v < worst && vi != q) {
                        bool c = v < lr;
                        unsigned bal = __ballot_sync(FULLMASK, c);
                        int pos = __ffs(bal) - 1;  // insertion position (<= 15)
                        float pr = __shfl_up_sync(FULLMASK, lr, 1);
                        int pi = __shfl_up_sync(FULLMASK, li, 1);
                        if (c) {
                            lr = (lane == pos) ? v : pr;
                            li = (lane == pos) ? vi : pi;
                        }
                        worst = __shfl_sync(FULLMASK, lr, KNN - 1);
                    }
                    act = __ballot_sync(FULLMASK, pm != 0);
                }
            }

            base = nbase;
            xa = nxa; xb = nxb; ya = nya; yb = nyb; sa = nsa; sb = nsb;
        }

        // ---- epilogue: exact Euclidean distance for the 16 winners ----
        float xj = xs[li];
        float yj = ys[li];
        float dx = xq - xj;
        float dy = yq - yj;
        float d = sqrtf(dx * dx + dy * dy);
        if (lane < KNN) out[q * KNN + lane] = d;
    }
}

extern "C" void kernel_launch(void* const* d_in, const int* in_sizes, int n_in,
                              void* d_out, int out_size) {
    const float* p = (const float*)d_in[0];
    float* out = (float*)d_out;
    int n = in_sizes[0] / 3;  // points, each (x, y, z)

    int iters = (n - 32 + 255) / 256;
    int padn = 32 + (iters + 1) * 256;  // +1 tile so prefetch never goes OOB
    size_t smem = (size_t)3 * padn * sizeof(float);

    cudaFuncSetAttribute(knn_warpselect_kernel,
                         cudaFuncAttributeMaxDynamicSharedMemorySize, (int)smem);
    knn_warpselect_kernel<<<152, 256, smem>>>(p, out, n, padn, iters);
}

// round 2
// speedup vs baseline: 1.9862x; 1.9862x over previous
#include <cuda_runtime.h>

#define FULLMASK 0xFFFFFFFFu
#define KNN 16

// ---- packed f32x2 helpers (sm_103a FFMA2 path) ----
static __device__ __forceinline__ unsigned long long fma2(unsigned long long a,
                                                          unsigned long long b,
                                                          unsigned long long c) {
    unsigned long long d;
    asm("fma.rn.f32x2 %0, %1, %2, %3;" : "=l"(d) : "l"(a), "l"(b), "l"(c));
    return d;
}
static __device__ __forceinline__ unsigned long long pack2(float lo, float hi) {
    unsigned long long v;
    asm("mov.b64 %0, {%1, %2};"
        : "=l"(v) : "r"(__float_as_uint(lo)), "r"(__float_as_uint(hi)));
    return v;
}
static __device__ __forceinline__ void unpack2(unsigned long long v, float &lo, float &hi) {
    unsigned a, b;
    asm("mov.b64 {%0, %1}, %2;" : "=r"(a), "=r"(b) : "l"(v));
    lo = __uint_as_float(a);
    hi = __uint_as_float(b);
}

static __device__ __forceinline__ float sel8(float r0, float r1, float r2, float r3,
                                             float r4, float r5, float r6, float r7,
                                             int k) {
    float s01 = (k & 1) ? r1 : r0;
    float s23 = (k & 1) ? r3 : r2;
    float s45 = (k & 1) ? r5 : r4;
    float s67 = (k & 1) ? r7 : r6;
    float a = (k & 2) ? s23 : s01;
    float b = (k & 2) ? s67 : s45;
    return (k & 4) ? b : a;
}

__global__ void __launch_bounds__(1024, 1)
knn_warpselect_kernel(const float* __restrict__ p, float* __restrict__ out,
                      int n, int padn, int iters) {
    extern __shared__ float smem[];
    float* xs = smem;
    float* ys = smem + padn;
    float* sq = smem + 2 * padn;

    const int tid = threadIdx.x;

    // One-time SoA load of the whole point set into shared memory.
    for (int j = tid; j < padn; j += blockDim.x) {
        if (j < n) {
            float x = p[3 * j];
            float y = p[3 * j + 1];
            xs[j] = x;
            ys[j] = y;
            sq[j] = fmaf(x, x, y * y);
        } else {
            xs[j] = 0.0f;
            ys[j] = 0.0f;
            sq[j] = 3.0e38f;  // sentinel: never selected
        }
    }
    __syncthreads();

    const int lane = tid & 31;
    const int gw = blockIdx.x * (blockDim.x >> 5) + (tid >> 5);
    const int nwarps = gridDim.x * (blockDim.x >> 5);
    const int l4 = 4 * lane;  // conflict-free 16B lane stride

    for (int q = gw; q < n; q += nwarps) {
        const float xq = xs[q];
        const float yq = ys[q];
        const float cx = -2.0f * xq;
        const float cy = -2.0f * yq;
        const unsigned long long cx2 = pack2(cx, cx);
        const unsigned long long cy2 = pack2(cy, cy);

        // ---- prime: warp-bitonic sort of first 32 candidates (r, idx) ----
        float lr;
        int li;
        {
            float r = fmaf(cx, xs[lane], fmaf(cy, ys[lane], sq[lane]));
            int idx = lane;
            if (idx == q) r = 3.0e38f;  // exclude self
#pragma unroll
            for (int k = 2; k <= 32; k <<= 1) {
#pragma unroll
                for (int j = k >> 1; j > 0; j >>= 1) {
                    float orv = __shfl_xor_sync(FULLMASK, r, j);
                    int oiv = __shfl_xor_sync(FULLMASK, idx, j);
                    bool up = ((lane & k) == 0);
                    bool lower = ((lane & j) == 0);
                    bool takeMin = (lower == up);
                    bool sw = takeMin ? (orv < r) : (orv > r);
                    if (sw) { r = orv; idx = oiv; }
                }
            }
            lr = r;   // lane l holds l-th smallest r of first 32 candidates
            li = idx;
        }
        float worst = __shfl_sync(FULLMASK, lr, KNN - 1);

        // ---- main scan: 8 candidates/lane/iter ----
        // Lane l owns candidates {base+4l..+3} and {base+128+4l..+3}.
        // 16B lane stride -> conflict-free LDS.128 (8-lane phase covers 128B).
        int base = 32;
        ulonglong2 xa = *reinterpret_cast<const ulonglong2*>(xs + base + l4);
        ulonglong2 xb = *reinterpret_cast<const ulonglong2*>(xs + base + 128 + l4);
        ulonglong2 ya = *reinterpret_cast<const ulonglong2*>(ys + base + l4);
        ulonglong2 yb = *reinterpret_cast<const ulonglong2*>(ys + base + 128 + l4);
        ulonglong2 sa = *reinterpret_cast<const ulonglong2*>(sq + base + l4);
        ulonglong2 sb = *reinterpret_cast<const ulonglong2*>(sq + base + 128 + l4);

        for (int i = 0; i < iters; i++) {
            const int nbase = base + 256;
            // prefetch next tile (padding guarantees in-bounds)
            ulonglong2 nxa = *reinterpret_cast<const ulonglong2*>(xs + nbase + l4);
            ulonglong2 nxb = *reinterpret_cast<const ulonglong2*>(xs + nbase + 128 + l4);
            ulonglong2 nya = *reinterpret_cast<const ulonglong2*>(ys + nbase + l4);
            ulonglong2 nyb = *reinterpret_cast<const ulonglong2*>(ys + nbase + 128 + l4);
            ulonglong2 nsa = *reinterpret_cast<const ulonglong2*>(sq + nbase + l4);
            ulonglong2 nsb = *reinterpret_cast<const ulonglong2*>(sq + nbase + 128 + l4);

            unsigned long long ra = fma2(cx2, xa.x, fma2(cy2, ya.x, sa.x));
            unsigned long long rb = fma2(cx2, xa.y, fma2(cy2, ya.y, sa.y));
            unsigned long long rc = fma2(cx2, xb.x, fma2(cy2, yb.x, sb.x));
            unsigned long long rd = fma2(cx2, xb.y, fma2(cy2, yb.y, sb.y));
            float r0, r1, r2, r3, r4, r5, r6, r7;
            unpack2(ra, r0, r1);
            unpack2(rb, r2, r3);
            unpack2(rc, r4, r5);
            unpack2(rd, r6, r7);

            float m = fminf(fminf(fminf(r0, r1), fminf(r2, r3)),
                            fminf(fminf(r4, r5), fminf(r6, r7)));
            unsigned hb = __ballot_sync(FULLMASK, m < worst);
            if (hb) {
                // per-lane pass mask over the 8 screened candidates
                unsigned pm = 0;
                pm |= (r0 < worst) ? 1u : 0u;
                pm |= (r1 < worst) ? 2u : 0u;
                pm |= (r2 < worst) ? 4u : 0u;
                pm |= (r3 < worst) ? 8u : 0u;
                pm |= (r4 < worst) ? 16u : 0u;
                pm |= (r5 < worst) ? 32u : 0u;
                pm |= (r6 < worst) ? 64u : 0u;
                pm |= (r7 < worst) ? 128u : 0u;

                int k0 = __ffs(pm) - 1;
                float vs = sel8(r0, r1, r2, r3, r4, r5, r6, r7, k0);
                int vis = base + l4 + (k0 & 3) + ((k0 & 4) ? 128 : 0);

                unsigned act = __ballot_sync(FULLMASK, pm != 0);
                while (act) {
                    int src = __ffs(act) - 1;
                    float v = __shfl_sync(FULLMASK, vs, src);
                    int vi = __shfl_sync(FULLMASK, vis, src);
                    if (lane == src) {
                        pm &= pm - 1;
                        int k = __ffs(pm) - 1;
                        vs = sel8(r0, r1, r2, r3, r4, r5, r6, r7, k);
                        vis = base + l4 + (k & 3) + ((k & 4) ? 128 : 0);
                    }
                    // re-check against (possibly tightened) threshold; skip self
                    if (v < worst && vi != q) {
                        bool c = v < lr;
                        unsigned bal = __ballot_sync(FULLMASK, c);
                        int pos = __ffs(bal) - 1;  // insertion position (<= 15)
                        float pr = __shfl_up_sync(FULLMASK, lr, 1);
                        int pi = __shfl_up_sync(FULLMASK, li, 1);
                        if (c) {
                            lr = (lane == pos) ? v : pr;
                            li = (lane == pos) ? vi : pi;
                        }
                        worst = __shfl_sync(FULLMASK, lr, KNN - 1);
                    }
                    act = __ballot_sync(FULLMASK, pm != 0);
                }
            }

            base = nbase;
            xa = nxa; xb = nxb; ya = nya; yb = nyb; sa = nsa; sb = nsb;
        }

        // ---- epilogue: exact Euclidean distance for the 16 winners ----
        float xj = xs[li];
        float yj = ys[li];
        float dx = xq - xj;
        float dy = yq - yj;
        float d = sqrtf(dx * dx + dy * dy);
        if (lane < KNN) out[q * KNN + lane] = d;
    }
}

extern "C" void kernel_launch(void* const* d_in, const int* in_sizes, int n_in,
                              void* d_out, int out_size) {
    const float* p = (const float*)d_in[0];
    float* out = (float*)d_out;
    int n = in_sizes[0] / 3;  // points, each (x, y, z)

    int iters = (n - 32 + 255) / 256;
    int padn = 32 + (iters + 1) * 256;  // +1 tile so prefetch never goes OOB
    size_t smem = (size_t)3 * padn * sizeof(float);

    cudaFuncSetAttribute(knn_warpselect_kernel,
                         cudaFuncAttributeMaxDynamicSharedMemorySize, (int)smem);
    knn_warpselect_kernel<<<152, 1024, smem>>>(p, out, n, padn, iters);
}

// round 3
// speedup vs baseline: 5.7609x; 2.9005x over previous
#include <cuda_runtime.h>

#define FULLMASK 0xFFFFFFFFu
#define KNN 16
#define NBINS 4096
#define XLO (-6.0f)
#define XRANGE 12.0f
#define BINW (XRANGE / (float)NBINS)   // 0.0029296875
#define PAD 64
#define NCAP 32768
#define RBIG 3.0e38f
#define MARGIN 1e-4f

// ---- scratch (no allocation allowed) ----
__device__ int   g_cnt[NBINS];
__device__ int   g_hist[NBINS];
__device__ int   g_binstart[NBINS + 1];
__device__ float g_sx[NCAP];
__device__ float g_sy[NCAP];
__device__ float g_ssq[NCAP];
__device__ int   g_sorig[NCAP];

static __device__ __forceinline__ int binof(float x) {
    int b = (int)((x - XLO) * ((float)NBINS / XRANGE));
    return min(max(b, 0), NBINS - 1);
}

// ---- packed f32x2 helpers ----
static __device__ __forceinline__ unsigned long long fma2(unsigned long long a,
                                                          unsigned long long b,
                                                          unsigned long long c) {
    unsigned long long d;
    asm("fma.rn.f32x2 %0, %1, %2, %3;" : "=l"(d) : "l"(a), "l"(b), "l"(c));
    return d;
}
static __device__ __forceinline__ unsigned long long pack2(float lo, float hi) {
    unsigned long long v;
    asm("mov.b64 %0, {%1, %2};"
        : "=l"(v) : "r"(__float_as_uint(lo)), "r"(__float_as_uint(hi)));
    return v;
}
static __device__ __forceinline__ void unpack2(unsigned long long v, float &lo, float &hi) {
    unsigned a, b;
    asm("mov.b64 {%0, %1}, %2;" : "=r"(a), "=r"(b) : "l"(v));
    lo = __uint_as_float(a);
    hi = __uint_as_float(b);
}

// ================= setup kernels =================
__global__ void zero_kernel() {
    int i = blockIdx.x * blockDim.x + threadIdx.x;
    if (i < NBINS) { g_cnt[i] = 0; g_hist[i] = 0; }
}

__global__ void hist_kernel(const float* __restrict__ p, int n) {
    int i = blockIdx.x * blockDim.x + threadIdx.x;
    if (i < n) atomicAdd(&g_hist[binof(p[3 * i])], 1);
}

__global__ void prefix_kernel() {
    __shared__ int wsum[32];
    int tid = threadIdx.x;                  // 1024 threads, 4 bins each
    int v0 = g_hist[tid * 4 + 0];
    int v1 = g_hist[tid * 4 + 1];
    int v2 = g_hist[tid * 4 + 2];
    int v3 = g_hist[tid * 4 + 3];
    int s = v0 + v1 + v2 + v3;
    int x = s;
#pragma unroll
    for (int d = 1; d < 32; d <<= 1) {
        int y = __shfl_up_sync(FULLMASK, x, d);
        if ((tid & 31) >= d) x += y;
    }
    if ((tid & 31) == 31) wsum[tid >> 5] = x;
    __syncthreads();
    if (tid < 32) {
        int w = wsum[tid];
#pragma unroll
        for (int d = 1; d < 32; d <<= 1) {
            int y = __shfl_up_sync(FULLMASK, w, d);
            if (tid >= d) w += y;
        }
        wsum[tid] = w;
    }
    __syncthreads();
    int ex = x - s + ((tid >> 5) ? wsum[(tid >> 5) - 1] : 0);
    g_binstart[tid * 4 + 0] = ex;
    g_binstart[tid * 4 + 1] = ex + v0;
    g_binstart[tid * 4 + 2] = ex + v0 + v1;
    g_binstart[tid * 4 + 3] = ex + v0 + v1 + v2;
    if (tid == 1023) g_binstart[NBINS] = ex + s;
}

__global__ void scatter_kernel(const float* __restrict__ p, int n) {
    int i = blockIdx.x * blockDim.x + threadIdx.x;
    if (i < n) {
        float x = p[3 * i];
        float y = p[3 * i + 1];
        int b = binof(x);
        int pos = g_binstart[b] + atomicAdd(&g_cnt[b], 1);
        g_sx[pos] = x;
        g_sy[pos] = y;
        g_ssq[pos] = fmaf(x, x, y * y);
        g_sorig[pos] = i;
    }
}

// ================= main kernel =================
__global__ void __launch_bounds__(1024, 1)
knn_sorted_kernel(float* __restrict__ out, int n, int padn) {
    extern __shared__ float smem[];
    float* xs = smem;
    float* ys = smem + padn;
    float* sv = smem + 2 * padn;

    const int tid = threadIdx.x;
    for (int j = tid; j < padn; j += blockDim.x) {
        int slot = j - PAD;
        if (slot >= 0 && slot < n) {
            xs[j] = g_sx[slot];
            ys[j] = g_sy[slot];
            sv[j] = g_ssq[slot];
        } else {
            xs[j] = (slot < 0) ? -1.0e9f : 1.0e9f;
            ys[j] = 0.0f;
            sv[j] = RBIG;    // r rounds to exactly RBIG -> never inserted
        }
    }
    __syncthreads();

    const float* px = xs + PAD;   // px[slot], valid slot in [-PAD, n+PAD)
    const float* py = ys + PAD;
    const float* psq = sv + PAD;

    const int lane = tid & 31;
    const int gw = blockIdx.x * (blockDim.x >> 5) + (tid >> 5);
    const int nwarps = gridDim.x * (blockDim.x >> 5);

    for (int s = gw; s < n; s += nwarps) {
        const float xq = px[s];
        const float yq = py[s];
        const float sqq = psq[s];
        const float cx = -2.0f * xq;
        const float cy = -2.0f * yq;
        const unsigned long long cx2 = pack2(cx, cx);
        const unsigned long long cy2 = pack2(cy, cy);

        // ---- prime: bitonic top-32 on window [A, A+31] (A even, contains s) ----
        const int A = (s - 16) & ~1;
        float lr;
        int li;
        {
            int cand = A + lane;
            float r = fmaf(cx, px[cand], fmaf(cy, py[cand], psq[cand]));
            if (cand == s) r = RBIG;
#pragma unroll
            for (int k = 2; k <= 32; k <<= 1) {
#pragma unroll
                for (int j = k >> 1; j > 0; j >>= 1) {
                    float orv = __shfl_xor_sync(FULLMASK, r, j);
                    int oiv = __shfl_xor_sync(FULLMASK, cand, j);
                    bool up = ((lane & k) == 0);
                    bool lower = ((lane & j) == 0);
                    bool takeMin = (lower == up);
                    bool sw = takeMin ? (orv < r) : (orv > r);
                    if (sw) { r = orv; cand = oiv; }
                }
            }
            lr = r;
            li = cand;
        }
        float worst = __shfl_sync(FULLMASK, lr, KNN - 1);

        // ---- outward scan with x-pruning; tiles of 64 (2 cands/lane) ----
        int L = A - 1;        // next left tile is [L-63, L]  (L odd -> even base)
        int R = A + 32;       // next right tile is [R, R+63] (R even)
        bool ldead = false, rdead = false;

#define SCAN_TILE(C0BASE)                                                      \
        {                                                                      \
            const int c0 = (C0BASE) + 2 * lane;                                \
            float2 xv = *reinterpret_cast<const float2*>(px + c0);             \
            float2 yv = *reinterpret_cast<const float2*>(py + c0);             \
            float2 qv = *reinterpret_cast<const float2*>(psq + c0);            \
            unsigned long long rr =                                            \
                fma2(cx2, pack2(xv.x, xv.y),                                   \
                     fma2(cy2, pack2(yv.x, yv.y), pack2(qv.x, qv.y)));         \
            float r0, r1;                                                      \
            unpack2(rr, r0, r1);                                               \
            unsigned hb = __ballot_sync(FULLMASK, fminf(r0, r1) < worst);      \
            if (hb) {                                                          \
                unsigned pm = (r0 < worst ? 1u : 0u) | (r1 < worst ? 2u : 0u); \
                float vs = (pm & 1u) ? r0 : r1;                                \
                int vis = c0 + ((pm & 1u) ? 0 : 1);                            \
                unsigned act = __ballot_sync(FULLMASK, pm != 0u);              \
                while (act) {                                                  \
                    int src = __ffs(act) - 1;                                  \
                    float v = __shfl_sync(FULLMASK, vs, src);                  \
                    int vi = __shfl_sync(FULLMASK, vis, src);                  \
                    if (lane == src) {                                         \
                        pm &= pm - 1u;                                         \
                        vs = r1;                                               \
                        vis = c0 + 1;                                          \
                    }                                                          \
                    if (v < worst) {                                           \
                        bool c = v < lr;                                       \
                        unsigned bal = __ballot_sync(FULLMASK, c);             \
                        int pos = __ffs(bal) - 1;                              \
                        float pr = __shfl_up_sync(FULLMASK, lr, 1);            \
                        int pi = __shfl_up_sync(FULLMASK, li, 1);              \
                        if (c) {                                               \
                            lr = (lane == pos) ? v : pr;                       \
                            li = (lane == pos) ? vi : pi;                      \
                        }                                                      \
                        worst = __shfl_sync(FULLMASK, lr, KNN - 1);            \
                    }                                                          \
                    act = __ballot_sync(FULLMASK, pm != 0u);                   \
                }                                                              \
            }                                                                  \
        }

        while (!(ldead && rdead)) {
            if (!rdead) {
                if (R >= n) {
                    rdead = true;
                } else {
                    float dxe = px[R] - xq - BINW;
                    if (dxe > 0.0f && fmaf(dxe, dxe, -sqq) > worst + MARGIN) {
                        rdead = true;
                    } else {
                        SCAN_TILE(R);
                        R += 64;
                    }
                }
            }
            if (!ldead) {
                if (L < 0) {
                    ldead = true;
                } else {
                    float dxe = xq - px[L] - BINW;
                    if (dxe > 0.0f && fmaf(dxe, dxe, -sqq) > worst + MARGIN) {
                        ldead = true;
                    } else {
                        SCAN_TILE(L - 63);
                        L -= 64;
                    }
                }
            }
        }
#undef SCAN_TILE

        // ---- epilogue: exact distances, scatter to original row ----
        float dx = xq - px[li];
        float dy = yq - py[li];
        float d = sqrtf(dx * dx + dy * dy);
        int orig = g_sorig[s];
        if (lane < KNN) out[orig * KNN + lane] = d;
    }
}

extern "C" void kernel_launch(void* const* d_in, const int* in_sizes, int n_in,
                              void* d_out, int out_size) {
    const float* p = (const float*)d_in[0];
    float* out = (float*)d_out;
    int n = in_sizes[0] / 3;

    int nb = (n + 1023) / 1024;
    zero_kernel<<<(NBINS + 1023) / 1024, 1024>>>();
    hist_kernel<<<nb, 1024>>>(p, n);
    prefix_kernel<<<1, 1024>>>();
    scatter_kernel<<<nb, 1024>>>(p, n);

    int padn = n + 2 * PAD;
    size_t smem = (size_t)3 * padn * sizeof(float);
    cudaFuncSetAttribute(knn_sorted_kernel,
                         cudaFuncAttributeMaxDynamicSharedMemorySize, (int)smem);
    knn_sorted_kernel<<<152, 1024, smem>>>(out, n, padn);
}